// round 4
// baseline (speedup 1.0000x reference)
#include <cuda_runtime.h>
#include <math.h>

// Problem shapes (fixed by the dataset)
#define BB  2
#define NC  512
#define NF  8192
#define MM  8192
#define TILE 2048
#define NT  256
#define EPSF 1e-12f

// ---------------- scratch (__device__ globals; no allocation allowed) ----------------
__device__ float g_nt[BB * NF * 3];        // gathered nearest target per fine point
__device__ float g_pf[BB][32][4];          // fine blocks: sum sqrt(d1), sum zf^2, sum znt^2, sum ydiff^2
__device__ float g_pt[BB][32][2];          // target blocks: sum sqrt(min over fine), sum sqrt(min over coarse)
__device__ float g_pc[BB][2];              // coarse blocks: sum sqrt(d1 coarse)
__device__ float g_pv[BB][32][2];          // volume partials: fine, new_target

// Deterministic in-block tree reduction
__device__ __forceinline__ float blockSum(float v, float* sh) {
    int t = threadIdx.x;
    sh[t] = v;
    __syncthreads();
#pragma unroll
    for (int s = NT / 2; s > 0; s >>= 1) {
        if (t < s) sh[t] += sh[t + s];
        __syncthreads();
    }
    float r = sh[0];
    __syncthreads();
    return r;
}

// Load a tile of points into SMEM as (x, y, z, |p|^2) float4s.
__device__ __forceinline__ void loadTile(float4* st, const float* __restrict__ src,
                                         int t0, int count) {
    for (int k = threadIdx.x; k < count; k += NT) {
        const int j = t0 + k;
        const float y0 = src[j * 3 + 0];
        const float y1 = src[j * 3 + 1];
        const float y2 = src[j * 3 + 2];
        st[k] = make_float4(y0, y1, y2, y0 * y0 + y1 * y1 + y2 * y2);
    }
}

// Exact same arithmetic as the R1-passing kernel:
//   xy = fmaf(qz, z, fmaf(qy, y, qx * x));  t = fmaf(-2, xy, yy)
__device__ __forceinline__ float pairDist(float qx, float qy, float qz, float4 p) {
    const float xy = fmaf(qz, p.z, fmaf(qy, p.y, qx * p.x));
    return fmaf(-2.0f, xy, p.w);
}

// Fused nearest-neighbor kernel.
// grid = (66, BB). blockIdx.x: [0,32) fine->target (argmin+gather),
//                              [32,64) target->{fine,coarse}, [64,66) coarse->target
__global__ void __launch_bounds__(NT) nn_kernel(const float* __restrict__ sc,
                                                const float* __restrict__ sf,
                                                const float* __restrict__ tp)
{
    __shared__ float4 st[TILE];
    __shared__ float  sred[NT];

    const int b   = blockIdx.y;
    const int bx  = blockIdx.x;
    const int tid = threadIdx.x;

    const float* tgt = tp + (size_t)b * MM * 3;
    const float* fin = sf + (size_t)b * NF * 3;
    const float* crs = sc + (size_t)b * NC * 3;

    if (bx < 32) {
        // ---- fine -> target: argmin + gather + stats ----
        const int qi = bx * NT + tid;
        const float qx = fin[qi * 3 + 0];
        const float qy = fin[qi * 3 + 1];
        const float qz = fin[qi * 3 + 2];
        const float qq = qx * qx + qy * qy + qz * qz;

        float bA = 3.0e38f, bB = 3.0e38f;
        int   jA = 0,       jB = 0;

        for (int t0 = 0; t0 < MM; t0 += TILE) {
            loadTile(st, tgt, t0, TILE);
            __syncthreads();
#pragma unroll 4
            for (int k = 0; k < TILE; k += 2) {
                const float tA = pairDist(qx, qy, qz, st[k]);
                if (tA < bA) { bA = tA; jA = t0 + k; }
                const float tB = pairDist(qx, qy, qz, st[k + 1]);
                if (tB < bB) { bB = tB; jB = t0 + k + 1; }
            }
            __syncthreads();
        }
        float best = bA; int jbest = jA;
        if (bB < bA) { best = bB; jbest = jB; }

        const float d  = fmaxf(qq + best, 0.0f);
        const float d1 = sqrtf(fmaxf(d, EPSF));

        const float nx = tgt[jbest * 3 + 0];
        const float ny = tgt[jbest * 3 + 1];
        const float nz = tgt[jbest * 3 + 2];
        const int o = (b * NF + qi) * 3;
        g_nt[o + 0] = nx; g_nt[o + 1] = ny; g_nt[o + 2] = nz;

        const float yd = qy - ny;
        const float r0 = blockSum(d1,      sred);
        const float r1 = blockSum(qz * qz, sred);
        const float r2 = blockSum(nz * nz, sred);
        const float r3 = blockSum(yd * yd, sred);
        if (tid == 0) {
            g_pf[b][bx][0] = r0; g_pf[b][bx][1] = r1;
            g_pf[b][bx][2] = r2; g_pf[b][bx][3] = r3;
        }
    } else if (bx < 64) {
        // ---- target -> fine (min) and target -> coarse (min) ----
        const int qj = (bx - 32) * NT + tid;
        const float qx = tgt[qj * 3 + 0];
        const float qy = tgt[qj * 3 + 1];
        const float qz = tgt[qj * 3 + 2];
        const float qq = qx * qx + qy * qy + qz * qz;

        float mfA = 3.0e38f, mfB = 3.0e38f;
        for (int t0 = 0; t0 < NF; t0 += TILE) {
            loadTile(st, fin, t0, TILE);
            __syncthreads();
#pragma unroll 4
            for (int k = 0; k < TILE; k += 2) {
                mfA = fminf(mfA, pairDist(qx, qy, qz, st[k]));
                mfB = fminf(mfB, pairDist(qx, qy, qz, st[k + 1]));
            }
            __syncthreads();
        }
        const float minF = fminf(mfA, mfB);

        // coarse tile (NC = 512 fits in one tile)
        loadTile(st, crs, 0, NC);
        __syncthreads();
        float mcA = 3.0e38f, mcB = 3.0e38f;
#pragma unroll 4
        for (int k = 0; k < NC; k += 2) {
            mcA = fminf(mcA, pairDist(qx, qy, qz, st[k]));
            mcB = fminf(mcB, pairDist(qx, qy, qz, st[k + 1]));
        }
        __syncthreads();
        const float minC = fminf(mcA, mcB);

        const float d2f = sqrtf(fmaxf(fmaxf(qq + minF, 0.0f), EPSF));
        const float d2c = sqrtf(fmaxf(fmaxf(qq + minC, 0.0f), EPSF));
        const float r0 = blockSum(d2f, sred);
        const float r1 = blockSum(d2c, sred);
        if (tid == 0) { g_pt[b][bx - 32][0] = r0; g_pt[b][bx - 32][1] = r1; }
    } else {
        // ---- coarse -> target (min) ----
        const int ci = (bx - 64) * NT + tid;
        const float qx = crs[ci * 3 + 0];
        const float qy = crs[ci * 3 + 1];
        const float qz = crs[ci * 3 + 2];
        const float qq = qx * qx + qy * qy + qz * qz;

        float mA = 3.0e38f, mB = 3.0e38f;
        for (int t0 = 0; t0 < MM; t0 += TILE) {
            loadTile(st, tgt, t0, TILE);
            __syncthreads();
#pragma unroll 4
            for (int k = 0; k < TILE; k += 2) {
                mA = fminf(mA, pairDist(qx, qy, qz, st[k]));
                mB = fminf(mB, pairDist(qx, qy, qz, st[k + 1]));
            }
            __syncthreads();
        }
        const float d1c = sqrtf(fmaxf(fmaxf(qq + fminf(mA, mB), 0.0f), EPSF));
        const float r0 = blockSum(d1c, sred);
        if (tid == 0) g_pc[b][bx - 64] = r0;
    }
}

// Wedge-product volume partials for source_fine and gathered new_target.
// grid = (32, BB), one thread per consecutive triple.
__global__ void __launch_bounds__(NT) volume_kernel(const float* __restrict__ sf)
{
    __shared__ float sred[NT];
    const int b   = blockIdx.y;
    const int bx  = blockIdx.x;
    const int tid = threadIdx.x;
    const int i   = bx * NT + tid;

    float vf = 0.0f, vn = 0.0f;
    if (i < NF - 2) {
        const float* p = sf + (size_t)b * NF * 3 + (size_t)i * 3;
        float a0 = p[0], a1 = p[1], a2 = p[2];
        float e0 = p[3], e1 = p[4], e2 = p[5];
        float c0 = p[6], c1 = p[7], c2 = p[8];
        float cx = a1 * e2 - a2 * e1;
        float cy = a2 * e0 - a0 * e2;
        float cz = a0 * e1 - a1 * e0;
        vf = cx * c0 + cy * c1 + cz * c2;

        const float* q = g_nt + ((size_t)b * NF + i) * 3;
        a0 = q[0]; a1 = q[1]; a2 = q[2];
        e0 = q[3]; e1 = q[4]; e2 = q[5];
        c0 = q[6]; c1 = q[7]; c2 = q[8];
        cx = a1 * e2 - a2 * e1;
        cy = a2 * e0 - a0 * e2;
        cz = a0 * e1 - a1 * e0;
        vn = cx * c0 + cy * c1 + cz * c2;
    }
    const float r0 = blockSum(vf, sred);
    const float r1 = blockSum(vn, sred);
    if (tid == 0) { g_pv[b][bx][0] = r0; g_pv[b][bx][1] = r1; }
}

// Single-thread deterministic combine of all partials into the scalar loss.
__global__ void finalize_kernel(float* __restrict__ out)
{
    float S1f = 0.0f, Syd = 0.0f, S2f = 0.0f, S2c = 0.0f, S1c = 0.0f;
    float szf[BB], sznt[BB], vfb[BB], vnb[BB];
#pragma unroll
    for (int b = 0; b < BB; b++) { szf[b] = sznt[b] = vfb[b] = vnb[b] = 0.0f; }

    for (int b = 0; b < BB; b++) {
        for (int k = 0; k < 32; k++) {
            S1f     += g_pf[b][k][0];
            szf[b]  += g_pf[b][k][1];
            sznt[b] += g_pf[b][k][2];
            Syd     += g_pf[b][k][3];
            S2f     += g_pt[b][k][0];
            S2c     += g_pt[b][k][1];
            vfb[b]  += g_pv[b][k][0];
            vnb[b]  += g_pv[b][k][1];
        }
        S1c += g_pc[b][0] + g_pc[b][1];
    }

    const float la_f = 0.5f * (S1f / (float)(BB * NF) + S2f / (float)(BB * MM));
    const float la_c = 0.5f * (S1c / (float)(BB * NC) + S2c / (float)(BB * MM));
    const float lref = Syd / (float)(BB * NF);

    float lrot = 0.0f, lgeo = 0.0f;
    for (int b = 0; b < BB; b++) {
        const float dr = sqrtf(szf[b]) - sqrtf(sznt[b]);
        lrot += dr * dr;
        const float dg = (vfb[b] - vnb[b]) * (1.0f / 6.0f);
        lgeo += dg * dg;
    }
    lrot *= (1.0f / (float)BB);
    lgeo *= (1.0f / (float)BB);

    out[0] = lrot + lref + la_c + la_f + lgeo;
}

extern "C" void kernel_launch(void* const* d_in, const int* in_sizes, int n_in,
                              void* d_out, int out_size)
{
    const float* sc = (const float*)d_in[0];  // source_coarse (B, 512, 3)
    const float* sf = (const float*)d_in[1];  // source_fine   (B, 8192, 3)
    const float* tp = (const float*)d_in[2];  // target_points (B, 8192, 3)
    float* out = (float*)d_out;

    dim3 g1(66, BB);
    nn_kernel<<<g1, NT>>>(sc, sf, tp);

    dim3 g2(32, BB);
    volume_kernel<<<g2, NT>>>(sf);

    finalize_kernel<<<1, 1>>>(out);
}

// round 5
// speedup vs baseline: 1.0198x; 1.0198x over previous
#include <cuda_runtime.h>
#include <math.h>

// Problem shapes (fixed by the dataset)
#define BB  2
#define NC  512
#define NF  8192
#define MM  8192
#define TILE 2048
#define NT  256
#define EPSF 1e-12f

// ---------------- scratch (__device__ globals; no allocation allowed) ----------------
__device__ float g_nt[BB * NF * 3];        // gathered nearest target per fine point
__device__ float g_pf[BB][32][4];          // fine blocks: sum sqrt(d1), sum zf^2, sum znt^2, sum ydiff^2
__device__ float g_pt[BB][32][2];          // target blocks: sum sqrt(min over fine), sum sqrt(min over coarse)
__device__ float g_pc[BB][2];              // coarse blocks: sum sqrt(d1 coarse)
__device__ float g_pv[BB][32][2];          // volume partials: fine, new_target

// Deterministic in-block tree reduction
__device__ __forceinline__ float blockSum(float v, float* sh) {
    int t = threadIdx.x;
    sh[t] = v;
    __syncthreads();
#pragma unroll
    for (int s = NT / 2; s > 0; s >>= 1) {
        if (t < s) sh[t] += sh[t + s];
        __syncthreads();
    }
    float r = sh[0];
    __syncthreads();
    return r;
}

// Load a tile of points into SMEM as (x, y, z, |p|^2) float4s.
__device__ __forceinline__ void loadTile(float4* st, const float* __restrict__ src,
                                         int t0, int count) {
    for (int k = threadIdx.x; k < count; k += NT) {
        const int j = t0 + k;
        const float y0 = src[j * 3 + 0];
        const float y1 = src[j * 3 + 1];
        const float y2 = src[j * 3 + 2];
        st[k] = make_float4(y0, y1, y2, y0 * y0 + y1 * y1 + y2 * y2);
    }
}

// Exact same arithmetic as the R1-passing kernel:
//   xy = fmaf(qz, z, fmaf(qy, y, qx * x));  t = fmaf(-2, xy, yy)
__device__ __forceinline__ float pairDist(float qx, float qy, float qz, float4 p) {
    const float xy = fmaf(qz, p.z, fmaf(qy, p.y, qx * p.x));
    return fmaf(-2.0f, xy, p.w);
}

// Fused nearest-neighbor kernel.
// grid = (66, BB). blockIdx.x: [0,32) fine->target (argmin+gather),
//                              [32,64) target->{fine,coarse}, [64,66) coarse->target
__global__ void __launch_bounds__(NT) nn_kernel(const float* __restrict__ sc,
                                                const float* __restrict__ sf,
                                                const float* __restrict__ tp)
{
    __shared__ float4 st[TILE];
    __shared__ float  sred[NT];

    const int b   = blockIdx.y;
    const int bx  = blockIdx.x;
    const int tid = threadIdx.x;

    const float* tgt = tp + (size_t)b * MM * 3;
    const float* fin = sf + (size_t)b * NF * 3;
    const float* crs = sc + (size_t)b * NC * 3;

    if (bx < 32) {
        // ---- fine -> target: argmin + gather + stats ----
        const int qi = bx * NT + tid;
        const float qx = fin[qi * 3 + 0];
        const float qy = fin[qi * 3 + 1];
        const float qz = fin[qi * 3 + 2];
        const float qq = qx * qx + qy * qy + qz * qz;

        float bA = 3.0e38f, bB = 3.0e38f;
        int   jA = 0,       jB = 0;

        for (int t0 = 0; t0 < MM; t0 += TILE) {
            loadTile(st, tgt, t0, TILE);
            __syncthreads();
#pragma unroll 4
            for (int k = 0; k < TILE; k += 2) {
                const float tA = pairDist(qx, qy, qz, st[k]);
                if (tA < bA) { bA = tA; jA = t0 + k; }
                const float tB = pairDist(qx, qy, qz, st[k + 1]);
                if (tB < bB) { bB = tB; jB = t0 + k + 1; }
            }
            __syncthreads();
        }
        float best = bA; int jbest = jA;
        if (bB < bA) { best = bB; jbest = jB; }

        const float d  = fmaxf(qq + best, 0.0f);
        const float d1 = sqrtf(fmaxf(d, EPSF));

        const float nx = tgt[jbest * 3 + 0];
        const float ny = tgt[jbest * 3 + 1];
        const float nz = tgt[jbest * 3 + 2];
        const int o = (b * NF + qi) * 3;
        g_nt[o + 0] = nx; g_nt[o + 1] = ny; g_nt[o + 2] = nz;

        const float yd = qy - ny;
        const float r0 = blockSum(d1,      sred);
        const float r1 = blockSum(qz * qz, sred);
        const float r2 = blockSum(nz * nz, sred);
        const float r3 = blockSum(yd * yd, sred);
        if (tid == 0) {
            g_pf[b][bx][0] = r0; g_pf[b][bx][1] = r1;
            g_pf[b][bx][2] = r2; g_pf[b][bx][3] = r3;
        }
    } else if (bx < 64) {
        // ---- target -> fine (min) and target -> coarse (min) ----
        const int qj = (bx - 32) * NT + tid;
        const float qx = tgt[qj * 3 + 0];
        const float qy = tgt[qj * 3 + 1];
        const float qz = tgt[qj * 3 + 2];
        const float qq = qx * qx + qy * qy + qz * qz;

        float mfA = 3.0e38f, mfB = 3.0e38f;
        for (int t0 = 0; t0 < NF; t0 += TILE) {
            loadTile(st, fin, t0, TILE);
            __syncthreads();
#pragma unroll 4
            for (int k = 0; k < TILE; k += 2) {
                mfA = fminf(mfA, pairDist(qx, qy, qz, st[k]));
                mfB = fminf(mfB, pairDist(qx, qy, qz, st[k + 1]));
            }
            __syncthreads();
        }
        const float minF = fminf(mfA, mfB);

        // coarse tile (NC = 512 fits in one tile)
        loadTile(st, crs, 0, NC);
        __syncthreads();
        float mcA = 3.0e38f, mcB = 3.0e38f;
#pragma unroll 4
        for (int k = 0; k < NC; k += 2) {
            mcA = fminf(mcA, pairDist(qx, qy, qz, st[k]));
            mcB = fminf(mcB, pairDist(qx, qy, qz, st[k + 1]));
        }
        __syncthreads();
        const float minC = fminf(mcA, mcB);

        const float d2f = sqrtf(fmaxf(fmaxf(qq + minF, 0.0f), EPSF));
        const float d2c = sqrtf(fmaxf(fmaxf(qq + minC, 0.0f), EPSF));
        const float r0 = blockSum(d2f, sred);
        const float r1 = blockSum(d2c, sred);
        if (tid == 0) { g_pt[b][bx - 32][0] = r0; g_pt[b][bx - 32][1] = r1; }
    } else {
        // ---- coarse -> target (min) ----
        const int ci = (bx - 64) * NT + tid;
        const float qx = crs[ci * 3 + 0];
        const float qy = crs[ci * 3 + 1];
        const float qz = crs[ci * 3 + 2];
        const float qq = qx * qx + qy * qy + qz * qz;

        float mA = 3.0e38f, mB = 3.0e38f;
        for (int t0 = 0; t0 < MM; t0 += TILE) {
            loadTile(st, tgt, t0, TILE);
            __syncthreads();
#pragma unroll 4
            for (int k = 0; k < TILE; k += 2) {
                mA = fminf(mA, pairDist(qx, qy, qz, st[k]));
                mB = fminf(mB, pairDist(qx, qy, qz, st[k + 1]));
            }
            __syncthreads();
        }
        const float d1c = sqrtf(fmaxf(fmaxf(qq + fminf(mA, mB), 0.0f), EPSF));
        const float r0 = blockSum(d1c, sred);
        if (tid == 0) g_pc[b][bx - 64] = r0;
    }
}

// Wedge-product volume partials for source_fine and gathered new_target.
// grid = (32, BB), one thread per consecutive triple.
__global__ void __launch_bounds__(NT) volume_kernel(const float* __restrict__ sf)
{
    __shared__ float sred[NT];
    const int b   = blockIdx.y;
    const int bx  = blockIdx.x;
    const int tid = threadIdx.x;
    const int i   = bx * NT + tid;

    float vf = 0.0f, vn = 0.0f;
    if (i < NF - 2) {
        const float* p = sf + (size_t)b * NF * 3 + (size_t)i * 3;
        float a0 = p[0], a1 = p[1], a2 = p[2];
        float e0 = p[3], e1 = p[4], e2 = p[5];
        float c0 = p[6], c1 = p[7], c2 = p[8];
        float cx = a1 * e2 - a2 * e1;
        float cy = a2 * e0 - a0 * e2;
        float cz = a0 * e1 - a1 * e0;
        vf = cx * c0 + cy * c1 + cz * c2;

        const float* q = g_nt + ((size_t)b * NF + i) * 3;
        a0 = q[0]; a1 = q[1]; a2 = q[2];
        e0 = q[3]; e1 = q[4]; e2 = q[5];
        c0 = q[6]; c1 = q[7]; c2 = q[8];
        cx = a1 * e2 - a2 * e1;
        cy = a2 * e0 - a0 * e2;
        cz = a0 * e1 - a1 * e0;
        vn = cx * c0 + cy * c1 + cz * c2;
    }
    const float r0 = blockSum(vf, sred);
    const float r1 = blockSum(vn, sred);
    if (tid == 0) { g_pv[b][bx][0] = r0; g_pv[b][bx][1] = r1; }
}

// Single-thread deterministic combine of all partials into the scalar loss.
__global__ void finalize_kernel(float* __restrict__ out)
{
    float S1f = 0.0f, Syd = 0.0f, S2f = 0.0f, S2c = 0.0f, S1c = 0.0f;
    float szf[BB], sznt[BB], vfb[BB], vnb[BB];
#pragma unroll
    for (int b = 0; b < BB; b++) { szf[b] = sznt[b] = vfb[b] = vnb[b] = 0.0f; }

    for (int b = 0; b < BB; b++) {
        for (int k = 0; k < 32; k++) {
            S1f     += g_pf[b][k][0];
            szf[b]  += g_pf[b][k][1];
            sznt[b] += g_pf[b][k][2];
            Syd     += g_pf[b][k][3];
            S2f     += g_pt[b][k][0];
            S2c     += g_pt[b][k][1];
            vfb[b]  += g_pv[b][k][0];
            vnb[b]  += g_pv[b][k][1];
        }
        S1c += g_pc[b][0] + g_pc[b][1];
    }

    const float la_f = 0.5f * (S1f / (float)(BB * NF) + S2f / (float)(BB * MM));
    const float la_c = 0.5f * (S1c / (float)(BB * NC) + S2c / (float)(BB * MM));
    const float lref = Syd / (float)(BB * NF);

    float lrot = 0.0f, lgeo = 0.0f;
    for (int b = 0; b < BB; b++) {
        const float dr = sqrtf(szf[b]) - sqrtf(sznt[b]);
        lrot += dr * dr;
        const float dg = (vfb[b] - vnb[b]) * (1.0f / 6.0f);
        lgeo += dg * dg;
    }
    lrot *= (1.0f / (float)BB);
    lgeo *= (1.0f / (float)BB);

    out[0] = lrot + lref + la_c + la_f + lgeo;
}

extern "C" void kernel_launch(void* const* d_in, const int* in_sizes, int n_in,
                              void* d_out, int out_size)
{
    const float* sc = (const float*)d_in[0];  // source_coarse (B, 512, 3)
    const float* sf = (const float*)d_in[1];  // source_fine   (B, 8192, 3)
    const float* tp = (const float*)d_in[2];  // target_points (B, 8192, 3)
    float* out = (float*)d_out;

    dim3 g1(66, BB);
    nn_kernel<<<g1, NT>>>(sc, sf, tp);

    dim3 g2(32, BB);
    volume_kernel<<<g2, NT>>>(sf);

    finalize_kernel<<<1, 1>>>(out);
}

// round 6
// speedup vs baseline: 1.2481x; 1.2239x over previous
#include <cuda_runtime.h>
#include <math.h>

// Problem shapes (fixed by the dataset)
#define BB    2
#define NC    512
#define NF    8192
#define MM    8192
#define NT    256
#define SLICE 2048      // targets per block slice
#define NSL   4         // slices (8192 / 2048)
#define QPT   4         // queries per thread (main roles)
#define EPSF  1e-12f

typedef unsigned long long ull;

// ---------------- scratch (__device__ globals; no allocation allowed) ----------------
__device__ float g_av [BB][NSL][NF];     // fine->target partial min value per slice
__device__ int   g_ai [BB][NSL][NF];     // fine->target partial argmin index per slice
__device__ float g_tv [BB][NSL][MM];     // target->fine partial min per slice
__device__ float g_tcv[BB][NSL][MM];     // target->coarse partial min per coarse sub-slice
__device__ float g_cv [BB][NSL][NC];     // coarse->target partial min per slice
__device__ float g_nt [BB * NF * 3];     // gathered nearest target per fine point
__device__ float g_pf [BB][32][4];       // fine combine blocks: sum d1, sum zf^2, sum znt^2, sum ydiff^2
__device__ float g_pt [BB][32][2];       // target combine blocks: sum d2f, sum d2c
__device__ float g_pc [BB][2];           // coarse combine blocks: sum d1c
__device__ float g_pv [BB][32][2];       // volume partials: fine, new_target

// ---------------- packed f32x2 helpers (per-half bit-identical to scalar) ----------------
__device__ __forceinline__ ull pack2(float lo, float hi) {
    ull r; asm("mov.b64 %0, {%1, %2};" : "=l"(r) : "f"(lo), "f"(hi)); return r;
}
__device__ __forceinline__ void unpack2(ull v, float& lo, float& hi) {
    asm("mov.b64 {%0, %1}, %2;" : "=f"(lo), "=f"(hi) : "l"(v));
}
__device__ __forceinline__ ull mul2(ull a, ull b) {
    ull r; asm("mul.rn.f32x2 %0, %1, %2;" : "=l"(r) : "l"(a), "l"(b)); return r;
}
__device__ __forceinline__ ull fma2(ull a, ull b, ull c) {
    ull r; asm("fma.rn.f32x2 %0, %1, %2, %3;" : "=l"(r) : "l"(a), "l"(b), "l"(c)); return r;
}

// Deterministic in-block tree reduction
__device__ __forceinline__ float blockSum(float v, float* sh) {
    int t = threadIdx.x;
    sh[t] = v;
    __syncthreads();
#pragma unroll
    for (int s = NT / 2; s > 0; s >>= 1) {
        if (t < s) sh[t] += sh[t + s];
        __syncthreads();
    }
    float r = sh[0];
    __syncthreads();
    return r;
}

// Load `count` points (count even) starting at src[t0] into pair-structs:
//   xy[p] = (x_{2p}, x_{2p+1}, y_{2p}, y_{2p+1}),  zw[p] = (z_{2p}, z_{2p+1}, w_{2p}, w_{2p+1})
__device__ __forceinline__ void loadPairs(float4* xy, float4* zw,
                                          const float* __restrict__ src,
                                          int t0, int count) {
    for (int p = threadIdx.x; p < count / 2; p += NT) {
        const int j0 = t0 + 2 * p;
        const float x0 = src[j0 * 3 + 0], y0 = src[j0 * 3 + 1], z0 = src[j0 * 3 + 2];
        const float x1 = src[j0 * 3 + 3], y1 = src[j0 * 3 + 4], z1 = src[j0 * 3 + 5];
        xy[p] = make_float4(x0, x1, y0, y1);
        zw[p] = make_float4(z0, z1,
                            x0 * x0 + y0 * y0 + z0 * z0,
                            x1 * x1 + y1 * y1 + z1 * z1);
    }
}

// Main pass: grid = (68, BB).
//  bx in [0,32):  fine->target argmin.  qblock = bx>>2, slice = bx&3
//  bx in [32,64): target->fine min + target->coarse min. same decomposition
//  bx in [64,68): coarse->target min. slice = bx-64, all 512 coarse queries (Q=2)
__global__ void __launch_bounds__(NT) nn_kernel(const float* __restrict__ sc,
                                                const float* __restrict__ sf,
                                                const float* __restrict__ tp)
{
    __shared__ float4 tXY[SLICE / 2], tZW[SLICE / 2];
    __shared__ float4 cXY[64], cZW[64];   // coarse sub-slice pairs (128 points)

    const int b   = blockIdx.y;
    const int bx  = blockIdx.x;
    const int tid = threadIdx.x;

    const float* tgt = tp + (size_t)b * MM * 3;
    const float* fin = sf + (size_t)b * NF * 3;
    const float* crs = sc + (size_t)b * NC * 3;

    if (bx < 32) {
        // ================= fine -> target : partial argmin over one slice =================
        const int qb    = bx >> 2;
        const int slice = bx & 3;
        const int base  = slice * SLICE;

        loadPairs(tXY, tZW, tgt, base, SLICE);

        ull qx2[QPT], qy2[QPT], qz2[QPT];
        float b0[QPT], b1[QPT];
        int   j0[QPT], j1[QPT];
#pragma unroll
        for (int q = 0; q < QPT; q++) {
            const int qi = qb * (NT * QPT) + q * NT + tid;
            const float qx = fin[qi * 3 + 0];
            const float qy = fin[qi * 3 + 1];
            const float qz = fin[qi * 3 + 2];
            qx2[q] = pack2(qx, qx); qy2[q] = pack2(qy, qy); qz2[q] = pack2(qz, qz);
            b0[q] = 3.0e38f; b1[q] = 3.0e38f; j0[q] = base; j1[q] = base + 1;
        }
        const ull NEG2 = pack2(-2.0f, -2.0f);
        __syncthreads();

#pragma unroll 2
        for (int p = 0; p < SLICE / 2; p++) {
            const float4 vxy = tXY[p];
            const float4 vzw = tZW[p];
            const ull X2 = pack2(vxy.x, vxy.y);
            const ull Y2 = pack2(vxy.z, vxy.w);
            const ull Z2 = pack2(vzw.x, vzw.y);
            const ull W2 = pack2(vzw.z, vzw.w);
            const int je = base + 2 * p;
#pragma unroll
            for (int q = 0; q < QPT; q++) {
                const ull xy2 = fma2(qz2[q], Z2, fma2(qy2[q], Y2, mul2(qx2[q], X2)));
                const ull t2  = fma2(NEG2, xy2, W2);
                float tlo, thi; unpack2(t2, tlo, thi);
                if (tlo < b0[q]) { b0[q] = tlo; j0[q] = je; }
                if (thi < b1[q]) { b1[q] = thi; j1[q] = je + 1; }
            }
        }
#pragma unroll
        for (int q = 0; q < QPT; q++) {
            const int qi = qb * (NT * QPT) + q * NT + tid;
            float best = b0[q]; int jb = j0[q];
            if (b1[q] < best) { best = b1[q]; jb = j1[q]; }
            g_av[b][slice][qi] = best;
            g_ai[b][slice][qi] = jb;
        }
    } else if (bx < 64) {
        // ============ target -> fine (min) and target -> coarse (min), one slice ============
        const int r     = bx - 32;
        const int qb    = r >> 2;
        const int slice = r & 3;
        const int base  = slice * SLICE;

        loadPairs(tXY, tZW, fin, base, SLICE);
        loadPairs(cXY, cZW, crs, slice * 128, 128);

        ull qx2[QPT], qy2[QPT], qz2[QPT];
        float mf[QPT * 2], mc[QPT * 2];
#pragma unroll
        for (int q = 0; q < QPT; q++) {
            const int qj = qb * (NT * QPT) + q * NT + tid;
            const float qx = tgt[qj * 3 + 0];
            const float qy = tgt[qj * 3 + 1];
            const float qz = tgt[qj * 3 + 2];
            qx2[q] = pack2(qx, qx); qy2[q] = pack2(qy, qy); qz2[q] = pack2(qz, qz);
            mf[2 * q] = 3.0e38f; mf[2 * q + 1] = 3.0e38f;
            mc[2 * q] = 3.0e38f; mc[2 * q + 1] = 3.0e38f;
        }
        const ull NEG2 = pack2(-2.0f, -2.0f);
        __syncthreads();

#pragma unroll 2
        for (int p = 0; p < SLICE / 2; p++) {
            const float4 vxy = tXY[p];
            const float4 vzw = tZW[p];
            const ull X2 = pack2(vxy.x, vxy.y);
            const ull Y2 = pack2(vxy.z, vxy.w);
            const ull Z2 = pack2(vzw.x, vzw.y);
            const ull W2 = pack2(vzw.z, vzw.w);
#pragma unroll
            for (int q = 0; q < QPT; q++) {
                const ull xy2 = fma2(qz2[q], Z2, fma2(qy2[q], Y2, mul2(qx2[q], X2)));
                const ull t2  = fma2(NEG2, xy2, W2);
                float tlo, thi; unpack2(t2, tlo, thi);
                mf[2 * q]     = fminf(mf[2 * q],     tlo);
                mf[2 * q + 1] = fminf(mf[2 * q + 1], thi);
            }
        }
#pragma unroll
        for (int p = 0; p < 64; p++) {
            const float4 vxy = cXY[p];
            const float4 vzw = cZW[p];
            const ull X2 = pack2(vxy.x, vxy.y);
            const ull Y2 = pack2(vxy.z, vxy.w);
            const ull Z2 = pack2(vzw.x, vzw.y);
            const ull W2 = pack2(vzw.z, vzw.w);
#pragma unroll
            for (int q = 0; q < QPT; q++) {
                const ull xy2 = fma2(qz2[q], Z2, fma2(qy2[q], Y2, mul2(qx2[q], X2)));
                const ull t2  = fma2(NEG2, xy2, W2);
                float tlo, thi; unpack2(t2, tlo, thi);
                mc[2 * q]     = fminf(mc[2 * q],     tlo);
                mc[2 * q + 1] = fminf(mc[2 * q + 1], thi);
            }
        }
#pragma unroll
        for (int q = 0; q < QPT; q++) {
            const int qj = qb * (NT * QPT) + q * NT + tid;
            g_tv [b][slice][qj] = fminf(mf[2 * q], mf[2 * q + 1]);
            g_tcv[b][slice][qj] = fminf(mc[2 * q], mc[2 * q + 1]);
        }
    } else {
        // ================= coarse -> target : partial min over one slice =================
        const int slice = bx - 64;
        const int base  = slice * SLICE;

        loadPairs(tXY, tZW, tgt, base, SLICE);

        ull qx2[2], qy2[2], qz2[2];
        float m[4];
#pragma unroll
        for (int q = 0; q < 2; q++) {
            const int ci = q * NT + tid;
            const float qx = crs[ci * 3 + 0];
            const float qy = crs[ci * 3 + 1];
            const float qz = crs[ci * 3 + 2];
            qx2[q] = pack2(qx, qx); qy2[q] = pack2(qy, qy); qz2[q] = pack2(qz, qz);
            m[2 * q] = 3.0e38f; m[2 * q + 1] = 3.0e38f;
        }
        const ull NEG2 = pack2(-2.0f, -2.0f);
        __syncthreads();

#pragma unroll 2
        for (int p = 0; p < SLICE / 2; p++) {
            const float4 vxy = tXY[p];
            const float4 vzw = tZW[p];
            const ull X2 = pack2(vxy.x, vxy.y);
            const ull Y2 = pack2(vxy.z, vxy.w);
            const ull Z2 = pack2(vzw.x, vzw.y);
            const ull W2 = pack2(vzw.z, vzw.w);
#pragma unroll
            for (int q = 0; q < 2; q++) {
                const ull xy2 = fma2(qz2[q], Z2, fma2(qy2[q], Y2, mul2(qx2[q], X2)));
                const ull t2  = fma2(NEG2, xy2, W2);
                float tlo, thi; unpack2(t2, tlo, thi);
                m[2 * q]     = fminf(m[2 * q],     tlo);
                m[2 * q + 1] = fminf(m[2 * q + 1], thi);
            }
        }
#pragma unroll
        for (int q = 0; q < 2; q++) {
            const int ci = q * NT + tid;
            g_cv[b][slice][ci] = fminf(m[2 * q], m[2 * q + 1]);
        }
    }
}

// Combine partial slices + per-query epilogue + block partial sums.
// grid = (66, BB): bx<32 fine, [32,64) target, [64,66) coarse
__global__ void __launch_bounds__(NT) combine_kernel(const float* __restrict__ sc,
                                                     const float* __restrict__ sf,
                                                     const float* __restrict__ tp)
{
    __shared__ float sred[NT];
    const int b   = blockIdx.y;
    const int bx  = blockIdx.x;
    const int tid = threadIdx.x;

    if (bx < 32) {
        const int qi = bx * NT + tid;
        // argmin across slices in ascending order (strict < keeps earliest)
        float best = g_av[b][0][qi]; int jb = g_ai[b][0][qi];
#pragma unroll
        for (int s = 1; s < NSL; s++) {
            const float v = g_av[b][s][qi];
            if (v < best) { best = v; jb = g_ai[b][s][qi]; }
        }
        const float* fin = sf + (size_t)b * NF * 3;
        const float* tgt = tp + (size_t)b * MM * 3;
        const float qx = fin[qi * 3 + 0];
        const float qy = fin[qi * 3 + 1];
        const float qz = fin[qi * 3 + 2];
        const float qq = qx * qx + qy * qy + qz * qz;

        const float d  = fmaxf(qq + best, 0.0f);
        const float d1 = sqrtf(fmaxf(d, EPSF));

        const float nx = tgt[jb * 3 + 0];
        const float ny = tgt[jb * 3 + 1];
        const float nz = tgt[jb * 3 + 2];
        const int o = (b * NF + qi) * 3;
        g_nt[o + 0] = nx; g_nt[o + 1] = ny; g_nt[o + 2] = nz;

        const float yd = qy - ny;
        const float r0 = blockSum(d1,      sred);
        const float r1 = blockSum(qz * qz, sred);
        const float r2 = blockSum(nz * nz, sred);
        const float r3 = blockSum(yd * yd, sred);
        if (tid == 0) {
            g_pf[b][bx][0] = r0; g_pf[b][bx][1] = r1;
            g_pf[b][bx][2] = r2; g_pf[b][bx][3] = r3;
        }
    } else if (bx < 64) {
        const int qj = (bx - 32) * NT + tid;
        float mF = g_tv[b][0][qj], mC = g_tcv[b][0][qj];
#pragma unroll
        for (int s = 1; s < NSL; s++) {
            mF = fminf(mF, g_tv[b][s][qj]);
            mC = fminf(mC, g_tcv[b][s][qj]);
        }
        const float* tgt = tp + (size_t)b * MM * 3;
        const float qx = tgt[qj * 3 + 0];
        const float qy = tgt[qj * 3 + 1];
        const float qz = tgt[qj * 3 + 2];
        const float qq = qx * qx + qy * qy + qz * qz;

        const float d2f = sqrtf(fmaxf(fmaxf(qq + mF, 0.0f), EPSF));
        const float d2c = sqrtf(fmaxf(fmaxf(qq + mC, 0.0f), EPSF));
        const float r0 = blockSum(d2f, sred);
        const float r1 = blockSum(d2c, sred);
        if (tid == 0) { g_pt[b][bx - 32][0] = r0; g_pt[b][bx - 32][1] = r1; }
    } else {
        const int ci = (bx - 64) * NT + tid;
        float m = g_cv[b][0][ci];
#pragma unroll
        for (int s = 1; s < NSL; s++) m = fminf(m, g_cv[b][s][ci]);

        const float* crs = sc + (size_t)b * NC * 3;
        const float qx = crs[ci * 3 + 0];
        const float qy = crs[ci * 3 + 1];
        const float qz = crs[ci * 3 + 2];
        const float qq = qx * qx + qy * qy + qz * qz;

        const float d1c = sqrtf(fmaxf(fmaxf(qq + m, 0.0f), EPSF));
        const float r0 = blockSum(d1c, sred);
        if (tid == 0) g_pc[b][bx - 64] = r0;
    }
}

// Wedge-product volume partials for source_fine and gathered new_target.
__global__ void __launch_bounds__(NT) volume_kernel(const float* __restrict__ sf)
{
    __shared__ float sred[NT];
    const int b   = blockIdx.y;
    const int bx  = blockIdx.x;
    const int tid = threadIdx.x;
    const int i   = bx * NT + tid;

    float vf = 0.0f, vn = 0.0f;
    if (i < NF - 2) {
        const float* p = sf + (size_t)b * NF * 3 + (size_t)i * 3;
        float a0 = p[0], a1 = p[1], a2 = p[2];
        float e0 = p[3], e1 = p[4], e2 = p[5];
        float c0 = p[6], c1 = p[7], c2 = p[8];
        float cx = a1 * e2 - a2 * e1;
        float cy = a2 * e0 - a0 * e2;
        float cz = a0 * e1 - a1 * e0;
        vf = cx * c0 + cy * c1 + cz * c2;

        const float* q = g_nt + ((size_t)b * NF + i) * 3;
        a0 = q[0]; a1 = q[1]; a2 = q[2];
        e0 = q[3]; e1 = q[4]; e2 = q[5];
        c0 = q[6]; c1 = q[7]; c2 = q[8];
        cx = a1 * e2 - a2 * e1;
        cy = a2 * e0 - a0 * e2;
        cz = a0 * e1 - a1 * e0;
        vn = cx * c0 + cy * c1 + cz * c2;
    }
    const float r0 = blockSum(vf, sred);
    const float r1 = blockSum(vn, sred);
    if (tid == 0) { g_pv[b][bx][0] = r0; g_pv[b][bx][1] = r1; }
}

// Single-thread deterministic combine of all partials into the scalar loss.
__global__ void finalize_kernel(float* __restrict__ out)
{
    float S1f = 0.0f, Syd = 0.0f, S2f = 0.0f, S2c = 0.0f, S1c = 0.0f;
    float szf[BB], sznt[BB], vfb[BB], vnb[BB];
#pragma unroll
    for (int b = 0; b < BB; b++) { szf[b] = sznt[b] = vfb[b] = vnb[b] = 0.0f; }

    for (int b = 0; b < BB; b++) {
        for (int k = 0; k < 32; k++) {
            S1f     += g_pf[b][k][0];
            szf[b]  += g_pf[b][k][1];
            sznt[b] += g_pf[b][k][2];
            Syd     += g_pf[b][k][3];
            S2f     += g_pt[b][k][0];
            S2c     += g_pt[b][k][1];
            vfb[b]  += g_pv[b][k][0];
            vnb[b]  += g_pv[b][k][1];
        }
        S1c += g_pc[b][0] + g_pc[b][1];
    }

    const float la_f = 0.5f * (S1f / (float)(BB * NF) + S2f / (float)(BB * MM));
    const float la_c = 0.5f * (S1c / (float)(BB * NC) + S2c / (float)(BB * MM));
    const float lref = Syd / (float)(BB * NF);

    float lrot = 0.0f, lgeo = 0.0f;
    for (int b = 0; b < BB; b++) {
        const float dr = sqrtf(szf[b]) - sqrtf(sznt[b]);
        lrot += dr * dr;
        const float dg = (vfb[b] - vnb[b]) * (1.0f / 6.0f);
        lgeo += dg * dg;
    }
    lrot *= (1.0f / (float)BB);
    lgeo *= (1.0f / (float)BB);

    out[0] = lrot + lref + la_c + la_f + lgeo;
}

extern "C" void kernel_launch(void* const* d_in, const int* in_sizes, int n_in,
                              void* d_out, int out_size)
{
    const float* sc = (const float*)d_in[0];  // source_coarse (B, 512, 3)
    const float* sf = (const float*)d_in[1];  // source_fine   (B, 8192, 3)
    const float* tp = (const float*)d_in[2];  // target_points (B, 8192, 3)
    float* out = (float*)d_out;

    dim3 g1(68, BB);
    nn_kernel<<<g1, NT>>>(sc, sf, tp);

    dim3 g2(66, BB);
    combine_kernel<<<g2, NT>>>(sc, sf, tp);

    dim3 g3(32, BB);
    volume_kernel<<<g3, NT>>>(sf);

    finalize_kernel<<<1, 1>>>(out);
}